// round 7
// baseline (speedup 1.0000x reference)
#include <cuda_runtime.h>

#define BB 4
#define CC 64
#define HH 128
#define WW 128
#define GG 16
#define KK 7
#define CRR 16
#define HW (HH*WW)            // 16384
#define CHW (CC*HW)           // 1048576
#define NPIX (BB*HW)          // 65536
#define STAT_BLOCKS 256

// Scratch (device globals: allocation-guard safe)
__device__ float g_dw[BB*CHW];            // depthwise output, 16MB
__device__ float g_h [BB*CHW];            // pointwise output (involution "features"), 16MB
__device__ float g_r [BB*CRR*HW];         // reduce output (pre-BN), 4MB
__device__ float g_psum[CRR*STAT_BLOCKS];
__device__ float g_psq [CRR*STAT_BLOCKS];
__device__ float g_scale[CRR];
__device__ float g_bias [CRR];

// ---------------------------------------------------------------------------
// Kernel A: depthwise 3x3 conv, pad 1. One thread = one float4 quad of pixels.
// ---------------------------------------------------------------------------
__global__ void k_dw(const float* __restrict__ x, const float* __restrict__ wdw) {
    int t = blockIdx.x * blockDim.x + threadIdx.x;   // 0 .. 1048575
    int xq = t & 31;            // quad index in row (32 quads of 4)
    int y  = (t >> 5) & 127;
    int c  = (t >> 12) & 63;
    int b  = t >> 18;

    float w[9];
    const float* wp = wdw + c * 9;
#pragma unroll
    for (int i = 0; i < 9; i++) w[i] = __ldg(wp + i);

    float a0 = 0.f, a1 = 0.f, a2 = 0.f, a3 = 0.f;
    const float* base = x + (size_t)(b * 64 + c) * HW;
    int x0 = xq * 4;
#pragma unroll
    for (int dy = -1; dy <= 1; dy++) {
        int yy = y + dy;
        if (yy < 0 || yy >= HH) continue;
        const float* row = base + yy * WW;
        float v[6];
#pragma unroll
        for (int j = 0; j < 6; j++) {
            int xx = x0 - 1 + j;
            v[j] = (xx >= 0 && xx < WW) ? row[xx] : 0.f;
        }
#pragma unroll
        for (int kx = 0; kx < 3; kx++) {
            float wv = w[(dy + 1) * 3 + kx];
            a0 = fmaf(wv, v[kx + 0], a0);
            a1 = fmaf(wv, v[kx + 1], a1);
            a2 = fmaf(wv, v[kx + 2], a2);
            a3 = fmaf(wv, v[kx + 3], a3);
        }
    }
    float4* dst = (float4*)(g_dw + (size_t)(b * 64 + c) * HW + y * WW + x0);
    *dst = make_float4(a0, a1, a2, a3);
}

// ---------------------------------------------------------------------------
// Kernel B: pointwise 1x1, 64->64. Thread = (pixel quad, chunk of 16 outputs).
// grid (64, 4), block 256. Weights staged in shared.
// ---------------------------------------------------------------------------
__global__ void k_pw(const float* __restrict__ wpw) {
    __shared__ float wsh[64 * 64];
    int tid = threadIdx.x;
    for (int i = tid; i < 4096; i += 256) wsh[i] = wpw[i];
    __syncthreads();

    int quad = blockIdx.x * 256 + tid;    // 0..16383
    int oc0  = blockIdx.y * 16;           // output channel base
    int b  = quad >> 12;                  // 4096 quads per image
    int p4 = (quad & 4095) * 4;

    const float* src = g_dw + (size_t)b * CHW + p4;

    float4 acc[16];
#pragma unroll
    for (int o = 0; o < 16; o++) acc[o] = make_float4(0.f, 0.f, 0.f, 0.f);

#pragma unroll 4
    for (int c4 = 0; c4 < 16; c4++) {
        float4 v0 = *(const float4*)(src + (c4 * 4 + 0) * HW);
        float4 v1 = *(const float4*)(src + (c4 * 4 + 1) * HW);
        float4 v2 = *(const float4*)(src + (c4 * 4 + 2) * HW);
        float4 v3 = *(const float4*)(src + (c4 * 4 + 3) * HW);
#pragma unroll
        for (int o = 0; o < 16; o++) {
            float4 wv = *(const float4*)&wsh[(oc0 + o) * 64 + c4 * 4];
            acc[o].x = fmaf(wv.x, v0.x, fmaf(wv.y, v1.x, fmaf(wv.z, v2.x, fmaf(wv.w, v3.x, acc[o].x))));
            acc[o].y = fmaf(wv.x, v0.y, fmaf(wv.y, v1.y, fmaf(wv.z, v2.y, fmaf(wv.w, v3.y, acc[o].y))));
            acc[o].z = fmaf(wv.x, v0.z, fmaf(wv.y, v1.z, fmaf(wv.z, v2.z, fmaf(wv.w, v3.z, acc[o].z))));
            acc[o].w = fmaf(wv.x, v0.w, fmaf(wv.y, v1.w, fmaf(wv.z, v2.w, fmaf(wv.w, v3.w, acc[o].w))));
        }
    }
#pragma unroll
    for (int o = 0; o < 16; o++)
        *(float4*)(g_h + (size_t)b * CHW + (oc0 + o) * HW + p4) = acc[o];
}

// ---------------------------------------------------------------------------
// Kernel C: reduce 64->16 (r) + deterministic per-block BN partial stats.
// One thread per pixel. grid 256, block 256.
// ---------------------------------------------------------------------------
__global__ void k_reduce(const float* __restrict__ x, const float* __restrict__ wred) {
    __shared__ float wt[64 * 16];         // transposed: wt[c*16 + cr]
    __shared__ float sm_s[16][8];
    __shared__ float sm_q[16][8];
    int tid = threadIdx.x;
    for (int i = tid; i < 1024; i += 256) {
        int cr = i >> 6, c = i & 63;
        wt[c * 16 + cr] = wred[i];
    }
    __syncthreads();

    int pix = blockIdx.x * 256 + tid;     // 0..65535
    int b = pix >> 14;
    int p = pix & 16383;
    const float* src = x + (size_t)b * CHW + p;

    float acc[16];
#pragma unroll
    for (int i = 0; i < 16; i++) acc[i] = 0.f;

    for (int c = 0; c < 64; c++) {
        float v = src[c * HW];
        const float4* w4 = (const float4*)&wt[c * 16];
        float4 w0 = w4[0], w1 = w4[1], w2 = w4[2], w3 = w4[3];
        acc[0]  = fmaf(w0.x, v, acc[0]);  acc[1]  = fmaf(w0.y, v, acc[1]);
        acc[2]  = fmaf(w0.z, v, acc[2]);  acc[3]  = fmaf(w0.w, v, acc[3]);
        acc[4]  = fmaf(w1.x, v, acc[4]);  acc[5]  = fmaf(w1.y, v, acc[5]);
        acc[6]  = fmaf(w1.z, v, acc[6]);  acc[7]  = fmaf(w1.w, v, acc[7]);
        acc[8]  = fmaf(w2.x, v, acc[8]);  acc[9]  = fmaf(w2.y, v, acc[9]);
        acc[10] = fmaf(w2.z, v, acc[10]); acc[11] = fmaf(w2.w, v, acc[11]);
        acc[12] = fmaf(w3.x, v, acc[12]); acc[13] = fmaf(w3.y, v, acc[13]);
        acc[14] = fmaf(w3.z, v, acc[14]); acc[15] = fmaf(w3.w, v, acc[15]);
    }

    float* rdst = g_r + (size_t)b * (CRR * HW) + p;
#pragma unroll
    for (int cr = 0; cr < 16; cr++) rdst[cr * HW] = acc[cr];

    // deterministic block reduction of sum / sumsq per channel
    int lane = tid & 31, warp = tid >> 5;
#pragma unroll
    for (int cr = 0; cr < 16; cr++) {
        float s = acc[cr];
        float q = acc[cr] * acc[cr];
#pragma unroll
        for (int off = 16; off; off >>= 1) {
            s += __shfl_down_sync(0xFFFFFFFFu, s, off);
            q += __shfl_down_sync(0xFFFFFFFFu, q, off);
        }
        if (lane == 0) { sm_s[cr][warp] = s; sm_q[cr][warp] = q; }
    }
    __syncthreads();
    if (tid < 16) {
        float s = 0.f, q = 0.f;
#pragma unroll
        for (int w = 0; w < 8; w++) { s += sm_s[tid][w]; q += sm_q[tid][w]; }
        g_psum[tid * STAT_BLOCKS + blockIdx.x] = s;
        g_psq [tid * STAT_BLOCKS + blockIdx.x] = q;
    }
}

// ---------------------------------------------------------------------------
// Kernel D: finalize BN stats -> scale/bias. 1 block, 16 warps (one per cr).
// ---------------------------------------------------------------------------
__global__ void k_bnstats(const float* __restrict__ gamma, const float* __restrict__ beta) {
    int w = threadIdx.x >> 5;     // cr
    int lane = threadIdx.x & 31;
    float s = 0.f, q = 0.f;
    for (int i = lane; i < STAT_BLOCKS; i += 32) {
        s += g_psum[w * STAT_BLOCKS + i];
        q += g_psq [w * STAT_BLOCKS + i];
    }
#pragma unroll
    for (int off = 16; off; off >>= 1) {
        s += __shfl_down_sync(0xFFFFFFFFu, s, off);
        q += __shfl_down_sync(0xFFFFFFFFu, q, off);
    }
    if (lane == 0) {
        const float inv = 1.0f / (float)NPIX;
        float mean = s * inv;
        float var  = q * inv - mean * mean;
        float sc = gamma[w] * rsqrtf(var + 1e-5f);
        g_scale[w] = sc;
        g_bias[w]  = beta[w] - mean * sc;
    }
}

// ---------------------------------------------------------------------------
// Kernel E: fused BN+ReLU -> span GEMM (kern gen) -> involution (49 taps x 4 ch).
// grid (8, 8, B*G), block 256 (16x16 tile). h tile (4 ch packed float4) in shared.
// ---------------------------------------------------------------------------
__global__ __launch_bounds__(256, 2) void k_main(const float* __restrict__ wspan,
                                                 float* __restrict__ out) {
    __shared__ float4 hsh[22 * 22];
    __shared__ float  wsp[49 * 16];
    __shared__ float  ssc[16], sbi[16];

    int tid = threadIdx.x;
    int b = blockIdx.z >> 4;
    int g = blockIdx.z & 15;

    // stage span weights for this group
    const float* wsrc = wspan + g * 49 * 16;
    for (int i = tid; i < 784; i += 256) wsp[i] = wsrc[i];
    if (tid < 16) { ssc[tid] = g_scale[tid]; sbi[tid] = g_bias[tid]; }

    // stage h tile (4 channels of this group, packed) with halo 3
    int y0 = blockIdx.y * 16 - 3, x0 = blockIdx.x * 16 - 3;
    const float* hb = g_h + (size_t)b * CHW + (g * 4) * HW;
    for (int i = tid; i < 484; i += 256) {
        int ly = i / 22, lx = i - ly * 22;
        int yy = y0 + ly, xx = x0 + lx;
        float4 v = make_float4(0.f, 0.f, 0.f, 0.f);
        if ((unsigned)yy < (unsigned)HH && (unsigned)xx < (unsigned)WW) {
            int off = yy * WW + xx;
            v.x = hb[off];
            v.y = hb[off + HW];
            v.z = hb[off + 2 * HW];
            v.w = hb[off + 3 * HW];
        }
        hsh[i] = v;
    }
    __syncthreads();

    int ty = tid >> 4, tx = tid & 15;
    int y = blockIdx.y * 16 + ty, x = blockIdx.x * 16 + tx;

    // normalized + ReLU'd r for this pixel
    const float* rb = g_r + (size_t)b * (CRR * HW) + y * WW + x;
    float rn[16];
#pragma unroll
    for (int cr = 0; cr < 16; cr++)
        rn[cr] = fmaxf(fmaf(rb[cr * HW], ssc[cr], sbi[cr]), 0.f);

    // kernel generation: kern[kk] = sum_cr wsp[kk][cr] * rn[cr]
    float kern[49];
#pragma unroll
    for (int kk = 0; kk < 49; kk++) {
        const float4* w4 = (const float4*)&wsp[kk * 16];
        float4 w0 = w4[0], w1 = w4[1], w2 = w4[2], w3 = w4[3];
        float s;
        s = w0.x * rn[0];
        s = fmaf(w0.y, rn[1],  s);
        s = fmaf(w0.z, rn[2],  s);
        s = fmaf(w0.w, rn[3],  s);
        s = fmaf(w1.x, rn[4],  s);
        s = fmaf(w1.y, rn[5],  s);
        s = fmaf(w1.z, rn[6],  s);
        s = fmaf(w1.w, rn[7],  s);
        s = fmaf(w2.x, rn[8],  s);
        s = fmaf(w2.y, rn[9],  s);
        s = fmaf(w2.z, rn[10], s);
        s = fmaf(w2.w, rn[11], s);
        s = fmaf(w3.x, rn[12], s);
        s = fmaf(w3.y, rn[13], s);
        s = fmaf(w3.z, rn[14], s);
        s = fmaf(w3.w, rn[15], s);
        kern[kk] = s;
    }

    // involution: 49 taps x 4 channels (float4 packed)
    float ax = 0.f, ay = 0.f, az = 0.f, aw = 0.f;
#pragma unroll
    for (int ky = 0; ky < 7; ky++) {
#pragma unroll
        for (int kx = 0; kx < 7; kx++) {
            float4 hv = hsh[(ty + ky) * 22 + (tx + kx)];
            float kw = kern[ky * 7 + kx];
            ax = fmaf(kw, hv.x, ax);
            ay = fmaf(kw, hv.y, ay);
            az = fmaf(kw, hv.z, az);
            aw = fmaf(kw, hv.w, aw);
        }
    }

    float* ob = out + (size_t)b * CHW + (g * 4) * HW + y * WW + x;
    ob[0]      = ax;
    ob[HW]     = ay;
    ob[2 * HW] = az;
    ob[3 * HW] = aw;
}

// ---------------------------------------------------------------------------
extern "C" void kernel_launch(void* const* d_in, const int* in_sizes, int n_in,
                              void* d_out, int out_size) {
    const float* x      = (const float*)d_in[0];   // input  [4,64,128,128]
    const float* w_dw   = (const float*)d_in[1];   // [64,1,3,3]
    const float* w_pw   = (const float*)d_in[2];   // [64,64]
    const float* gamma  = (const float*)d_in[3];   // [16]
    const float* beta   = (const float*)d_in[4];   // [16]
    const float* w_red  = (const float*)d_in[5];   // [16,64]
    const float* w_span = (const float*)d_in[6];   // [784,16]
    float* out = (float*)d_out;

    k_dw<<<4096, 256>>>(x, w_dw);
    k_pw<<<dim3(64, 4), 256>>>(w_pw);
    k_reduce<<<STAT_BLOCKS, 256>>>(x, w_red);
    k_bnstats<<<1, 512>>>(gamma, beta);
    k_main<<<dim3(8, 8, BB * GG), 256>>>(w_span, out);
}

// round 8
// speedup vs baseline: 1.0479x; 1.0479x over previous
#include <cuda_runtime.h>

#define BB 4
#define CC 64
#define HH 128
#define WW 128
#define GG 16
#define KK 7
#define CRR 16
#define HW (HH*WW)            // 16384
#define CHW (CC*HW)           // 1048576
#define NPIX (BB*HW)          // 65536
#define STAT_BLOCKS 256
#define EPSBN 1e-5f

typedef unsigned long long u64;

// ---- packed f32x2 helpers (FFMA2 path; ptxas never auto-fuses) ----
__device__ __forceinline__ u64 pk(float lo, float hi) {
    u64 r; asm("mov.b64 %0,{%1,%2};" : "=l"(r) : "f"(lo), "f"(hi)); return r;
}
__device__ __forceinline__ u64 dup2(float v) { return pk(v, v); }
__device__ __forceinline__ void up(u64 v, float& lo, float& hi) {
    asm("mov.b64 {%0,%1},%2;" : "=f"(lo), "=f"(hi) : "l"(v));
}
__device__ __forceinline__ u64 fma2(u64 a, u64 b, u64 c) {
    u64 d; asm("fma.rn.f32x2 %0,%1,%2,%3;" : "=l"(d) : "l"(a), "l"(b), "l"(c)); return d;
}
__device__ __forceinline__ u64 mul2(u64 a, u64 b) {
    u64 d; asm("mul.rn.f32x2 %0,%1,%2;" : "=l"(d) : "l"(a), "l"(b)); return d;
}

// Scratch (device globals: allocation-guard safe)
__device__ float g_dw[BB*CHW];            // depthwise output, 16MB
__device__ float g_h [BB*CHW];            // pointwise output, 16MB
__device__ float g_r [BB*CRR*HW];         // reduce output (pre-BN), 4MB
__device__ float g_psum[CRR*STAT_BLOCKS];
__device__ float g_psq [CRR*STAT_BLOCKS];

// ---------------------------------------------------------------------------
// Kernel A: depthwise 3x3 conv, pad 1. One thread = one float4 quad of pixels.
// ---------------------------------------------------------------------------
__global__ void k_dw(const float* __restrict__ x, const float* __restrict__ wdw) {
    int t = blockIdx.x * blockDim.x + threadIdx.x;   // 0 .. 1048575
    int xq = t & 31;
    int y  = (t >> 5) & 127;
    int c  = (t >> 12) & 63;
    int b  = t >> 18;

    float w[9];
    const float* wp = wdw + c * 9;
#pragma unroll
    for (int i = 0; i < 9; i++) w[i] = __ldg(wp + i);

    float a0 = 0.f, a1 = 0.f, a2 = 0.f, a3 = 0.f;
    const float* base = x + (size_t)(b * 64 + c) * HW;
    int x0 = xq * 4;
#pragma unroll
    for (int dy = -1; dy <= 1; dy++) {
        int yy = y + dy;
        if (yy < 0 || yy >= HH) continue;
        const float* row = base + yy * WW;
        float v[6];
#pragma unroll
        for (int j = 0; j < 6; j++) {
            int xx = x0 - 1 + j;
            v[j] = (xx >= 0 && xx < WW) ? row[xx] : 0.f;
        }
#pragma unroll
        for (int kx = 0; kx < 3; kx++) {
            float wv = w[(dy + 1) * 3 + kx];
            a0 = fmaf(wv, v[kx + 0], a0);
            a1 = fmaf(wv, v[kx + 1], a1);
            a2 = fmaf(wv, v[kx + 2], a2);
            a3 = fmaf(wv, v[kx + 3], a3);
        }
    }
    float4* dst = (float4*)(g_dw + (size_t)(b * 64 + c) * HW + y * WW + x0);
    *dst = make_float4(a0, a1, a2, a3);
}

// ---------------------------------------------------------------------------
// Kernel B: pointwise 1x1, 64->64, FFMA2 over output-channel pairs.
// grid (64, 4), block 256. Thread = pixel quad x 16 outputs (8 o-pairs).
// ---------------------------------------------------------------------------
__global__ __launch_bounds__(256) void k_pw(const float* __restrict__ wpw) {
    __shared__ u64 wsh2[64 * 8];   // [c][opl] = (w[oc0+2opl][c], w[oc0+2opl+1][c])
    int tid = threadIdx.x;
    int oc0 = blockIdx.y * 16;
    for (int i = tid; i < 512; i += 256) {
        int c = i >> 3, opl = i & 7;
        wsh2[i] = pk(wpw[(oc0 + 2 * opl) * 64 + c], wpw[(oc0 + 2 * opl + 1) * 64 + c]);
    }
    __syncthreads();

    int quad = blockIdx.x * 256 + tid;    // 0..16383
    int b  = quad >> 12;
    int p4 = (quad & 4095) * 4;
    const float* src = g_dw + (size_t)b * CHW + p4;

    u64 acc[8][4];
#pragma unroll
    for (int o = 0; o < 8; o++)
#pragma unroll
        for (int p = 0; p < 4; p++) acc[o][p] = 0ULL;

#pragma unroll 4
    for (int c = 0; c < 64; c++) {
        float4 v = *(const float4*)(src + c * HW);
        u64 d0 = dup2(v.x), d1 = dup2(v.y), d2 = dup2(v.z), d3 = dup2(v.w);
        const u64* wr = &wsh2[c * 8];
#pragma unroll
        for (int o = 0; o < 8; o++) {
            u64 w2 = wr[o];
            acc[o][0] = fma2(w2, d0, acc[o][0]);
            acc[o][1] = fma2(w2, d1, acc[o][1]);
            acc[o][2] = fma2(w2, d2, acc[o][2]);
            acc[o][3] = fma2(w2, d3, acc[o][3]);
        }
    }

    float* dst = g_h + (size_t)b * CHW + p4;
#pragma unroll
    for (int o = 0; o < 8; o++) {
        float l0, h0, l1, h1, l2, h2, l3, h3;
        up(acc[o][0], l0, h0); up(acc[o][1], l1, h1);
        up(acc[o][2], l2, h2); up(acc[o][3], l3, h3);
        *(float4*)(dst + (oc0 + 2 * o)     * HW) = make_float4(l0, l1, l2, l3);
        *(float4*)(dst + (oc0 + 2 * o + 1) * HW) = make_float4(h0, h1, h2, h3);
    }
}

// ---------------------------------------------------------------------------
// Kernel C: reduce 64->16 (FFMA2 over cr-pairs) + deterministic BN partials.
// One thread per pixel. grid 256, block 256.
// ---------------------------------------------------------------------------
__global__ void k_reduce(const float* __restrict__ x, const float* __restrict__ wred) {
    __shared__ u64 wt2[64 * 8];     // [c][crp] = (w[2crp][c], w[2crp+1][c])
    __shared__ float sm_s[16][8];
    __shared__ float sm_q[16][8];
    int tid = threadIdx.x;
    for (int i = tid; i < 512; i += 256) {
        int c = i >> 3, crp = i & 7;
        wt2[i] = pk(wred[(2 * crp) * 64 + c], wred[(2 * crp + 1) * 64 + c]);
    }
    __syncthreads();

    int pix = blockIdx.x * 256 + tid;     // 0..65535
    int b = pix >> 14;
    int p = pix & 16383;
    const float* src = x + (size_t)b * CHW + p;

    u64 acc[8];
#pragma unroll
    for (int i = 0; i < 8; i++) acc[i] = 0ULL;

#pragma unroll 4
    for (int c = 0; c < 64; c++) {
        u64 d = dup2(src[c * HW]);
        const u64* wr = &wt2[c * 8];
#pragma unroll
        for (int crp = 0; crp < 8; crp++)
            acc[crp] = fma2(wr[crp], d, acc[crp]);
    }

    float av[16];
#pragma unroll
    for (int crp = 0; crp < 8; crp++) up(acc[crp], av[2 * crp], av[2 * crp + 1]);

    float* rdst = g_r + (size_t)b * (CRR * HW) + p;
#pragma unroll
    for (int cr = 0; cr < 16; cr++) rdst[cr * HW] = av[cr];

    // deterministic block reduction of sum / sumsq per channel
    int lane = tid & 31, warp = tid >> 5;
#pragma unroll
    for (int cr = 0; cr < 16; cr++) {
        float s = av[cr];
        float q = av[cr] * av[cr];
#pragma unroll
        for (int off = 16; off; off >>= 1) {
            s += __shfl_down_sync(0xFFFFFFFFu, s, off);
            q += __shfl_down_sync(0xFFFFFFFFu, q, off);
        }
        if (lane == 0) { sm_s[cr][warp] = s; sm_q[cr][warp] = q; }
    }
    __syncthreads();
    if (tid < 16) {
        float s = 0.f, q = 0.f;
#pragma unroll
        for (int w = 0; w < 8; w++) { s += sm_s[tid][w]; q += sm_q[tid][w]; }
        g_psum[tid * STAT_BLOCKS + blockIdx.x] = s;
        g_psq [tid * STAT_BLOCKS + blockIdx.x] = q;
    }
}

// ---------------------------------------------------------------------------
// Kernel D (main, fused): BN-finalize prologue (redundant per block) ->
// BN+ReLU -> span GEMM (FFMA2 cr-pairs) -> involution (FFMA2 channel-pairs).
// grid (8, 8, B*G), block 256 (16x16 tile).
// ---------------------------------------------------------------------------
__global__ __launch_bounds__(256, 2) void k_main(const float* __restrict__ wspan,
                                                 float* __restrict__ out,
                                                 const float* __restrict__ gamma,
                                                 const float* __restrict__ beta) {
    __shared__ ulonglong2 hsh[22 * 22];   // (ch01, ch23) packed pairs
    __shared__ u64  wsp2[49 * 8];         // span weights, cr-pairs
    __shared__ float ssc[16], sbi[16];

    int tid = threadIdx.x;
    int b = blockIdx.z >> 4;
    int g = blockIdx.z & 15;

    // stage span weights for this group (u64 = contiguous cr pair)
    const u64* wsrc = (const u64*)(wspan + g * 784);
    for (int i = tid; i < 392; i += 256) wsp2[i] = wsrc[i];

    // stage h tile (4 ch of this group, packed as two f32x2) with halo 3
    int y0 = blockIdx.y * 16 - 3, x0 = blockIdx.x * 16 - 3;
    const float* hb = g_h + (size_t)b * CHW + (g * 4) * HW;
    for (int i = tid; i < 484; i += 256) {
        int ly = i / 22, lx = i - ly * 22;
        int yy = y0 + ly, xx = x0 + lx;
        u64 a = 0ULL, c = 0ULL;
        if ((unsigned)yy < (unsigned)HH && (unsigned)xx < (unsigned)WW) {
            int off = yy * WW + xx;
            a = pk(hb[off], hb[off + HW]);
            c = pk(hb[off + 2 * HW], hb[off + 3 * HW]);
        }
        ulonglong2 hv; hv.x = a; hv.y = c;
        hsh[i] = hv;
    }

    // BN finalize (redundant per block; deterministic fixed-order sums).
    // Warp w handles cr = w and cr = w + 8.
    int warp = tid >> 5, lane = tid & 31;
#pragma unroll
    for (int rep = 0; rep < 2; rep++) {
        int cr = warp + rep * 8;
        float s = 0.f, q = 0.f;
        for (int i = lane; i < STAT_BLOCKS; i += 32) {
            s += g_psum[cr * STAT_BLOCKS + i];
            q += g_psq [cr * STAT_BLOCKS + i];
        }
#pragma unroll
        for (int off = 16; off; off >>= 1) {
            s += __shfl_down_sync(0xFFFFFFFFu, s, off);
            q += __shfl_down_sync(0xFFFFFFFFu, q, off);
        }
        if (lane == 0) {
            const float inv = 1.0f / (float)NPIX;
            float mean = s * inv;
            float var  = q * inv - mean * mean;
            float sc = gamma[cr] * rsqrtf(var + EPSBN);
            ssc[cr] = sc;
            sbi[cr] = beta[cr] - mean * sc;
        }
    }
    __syncthreads();

    int ty = tid >> 4, tx = tid & 15;
    int y = blockIdx.y * 16 + ty, x = blockIdx.x * 16 + tx;

    // normalized + ReLU'd r for this pixel, packed into cr-pairs
    const float* rb = g_r + (size_t)b * (CRR * HW) + y * WW + x;
    u64 rn2[8];
#pragma unroll
    for (int crp = 0; crp < 8; crp++) {
        int cr = 2 * crp;
        float r0 = fmaxf(fmaf(rb[cr * HW],       ssc[cr],     sbi[cr]),     0.f);
        float r1 = fmaxf(fmaf(rb[(cr + 1) * HW], ssc[cr + 1], sbi[cr + 1]), 0.f);
        rn2[crp] = pk(r0, r1);
    }

    // kernel generation: kern[kk] = sum_cr wsp[kk][cr] * rn[cr]  (FFMA2 + hadd)
    float kern[49];
#pragma unroll
    for (int kk = 0; kk < 49; kk++) {
        const u64* w = &wsp2[kk * 8];
        u64 a = mul2(w[0], rn2[0]);
        a = fma2(w[1], rn2[1], a);
        a = fma2(w[2], rn2[2], a);
        a = fma2(w[3], rn2[3], a);
        a = fma2(w[4], rn2[4], a);
        a = fma2(w[5], rn2[5], a);
        a = fma2(w[6], rn2[6], a);
        a = fma2(w[7], rn2[7], a);
        float l, h; up(a, l, h);
        kern[kk] = l + h;
    }

    // involution: 49 taps x 4 channels, two FFMA2 per tap
    u64 axy = 0ULL, azw = 0ULL;
#pragma unroll
    for (int ky = 0; ky < 7; ky++) {
#pragma unroll
        for (int kx = 0; kx < 7; kx++) {
            ulonglong2 hv = hsh[(ty + ky) * 22 + (tx + kx)];
            u64 kd = dup2(kern[ky * 7 + kx]);
            axy = fma2(kd, hv.x, axy);
            azw = fma2(kd, hv.y, azw);
        }
    }

    float ax, ay, az, aw;
    up(axy, ax, ay); up(azw, az, aw);
    float* ob = out + (size_t)b * CHW + (g * 4) * HW + y * WW + x;
    ob[0]      = ax;
    ob[HW]     = ay;
    ob[2 * HW] = az;
    ob[3 * HW] = aw;
}

// ---------------------------------------------------------------------------
extern "C" void kernel_launch(void* const* d_in, const int* in_sizes, int n_in,
                              void* d_out, int out_size) {
    const float* x      = (const float*)d_in[0];   // input  [4,64,128,128]
    const float* w_dw   = (const float*)d_in[1];   // [64,1,3,3]
    const float* w_pw   = (const float*)d_in[2];   // [64,64]
    const float* gamma  = (const float*)d_in[3];   // [16]
    const float* beta   = (const float*)d_in[4];   // [16]
    const float* w_red  = (const float*)d_in[5];   // [16,64]
    const float* w_span = (const float*)d_in[6];   // [784,16]
    float* out = (float*)d_out;

    k_dw<<<4096, 256>>>(x, w_dw);
    k_pw<<<dim3(64, 4), 256>>>(w_pw);
    k_reduce<<<STAT_BLOCKS, 256>>>(x, w_red);
    k_main<<<dim3(8, 8, BB * GG), 256>>>(w_span, out, gamma, beta);
}

// round 12
// speedup vs baseline: 1.3520x; 1.2902x over previous
#include <cuda_runtime.h>

#define BB 4
#define CC 64
#define HH 128
#define WW 128
#define GG 16
#define KK 7
#define CRR 16
#define HW (HH*WW)            // 16384
#define CHW (CC*HW)           // 1048576
#define NPIX (BB*HW)          // 65536
#define STAT_BLOCKS 256
#define EPSBN 1e-5f

typedef unsigned long long u64;

// ---- packed f32x2 helpers (FFMA2 path; ptxas never auto-fuses) ----
__device__ __forceinline__ u64 pk(float lo, float hi) {
    u64 r; asm("mov.b64 %0,{%1,%2};" : "=l"(r) : "f"(lo), "f"(hi)); return r;
}
__device__ __forceinline__ u64 dup2(float v) { return pk(v, v); }
__device__ __forceinline__ void up(u64 v, float& lo, float& hi) {
    asm("mov.b64 {%0,%1},%2;" : "=f"(lo), "=f"(hi) : "l"(v));
}
__device__ __forceinline__ u64 fma2(u64 a, u64 b, u64 c) {
    u64 d; asm("fma.rn.f32x2 %0,%1,%2,%3;" : "=l"(d) : "l"(a), "l"(b), "l"(c)); return d;
}
__device__ __forceinline__ u64 mul2(u64 a, u64 b) {
    u64 d; asm("mul.rn.f32x2 %0,%1,%2;" : "=l"(d) : "l"(a), "l"(b)); return d;
}

// Scratch (device globals: allocation-guard safe)
__device__ float g_dw[BB*CHW];            // depthwise output, 16MB
__device__ float g_h [BB*CHW];            // pointwise output, 16MB
__device__ float g_r [BB*CRR*HW];         // reduce output (pre-BN), 4MB
__device__ float g_psum[CRR*STAT_BLOCKS];
__device__ float g_psq [CRR*STAT_BLOCKS];

// ---------------------------------------------------------------------------
// Kernel A: depthwise 3x3 conv, pad 1. One thread = one float4 quad of pixels.
// ---------------------------------------------------------------------------
__global__ void k_dw(const float* __restrict__ x, const float* __restrict__ wdw) {
    int t = blockIdx.x * blockDim.x + threadIdx.x;   // 0 .. 1048575
    int xq = t & 31;
    int y  = (t >> 5) & 127;
    int c  = (t >> 12) & 63;
    int b  = t >> 18;

    float w[9];
    const float* wp = wdw + c * 9;
#pragma unroll
    for (int i = 0; i < 9; i++) w[i] = __ldg(wp + i);

    float a0 = 0.f, a1 = 0.f, a2 = 0.f, a3 = 0.f;
    const float* base = x + (size_t)(b * 64 + c) * HW;
    int x0 = xq * 4;
#pragma unroll
    for (int dy = -1; dy <= 1; dy++) {
        int yy = y + dy;
        if (yy < 0 || yy >= HH) continue;
        const float* row = base + yy * WW;
        float v[6];
#pragma unroll
        for (int j = 0; j < 6; j++) {
            int xx = x0 - 1 + j;
            v[j] = (xx >= 0 && xx < WW) ? row[xx] : 0.f;
        }
#pragma unroll
        for (int kx = 0; kx < 3; kx++) {
            float wv = w[(dy + 1) * 3 + kx];
            a0 = fmaf(wv, v[kx + 0], a0);
            a1 = fmaf(wv, v[kx + 1], a1);
            a2 = fmaf(wv, v[kx + 2], a2);
            a3 = fmaf(wv, v[kx + 3], a3);
        }
    }
    float4* dst = (float4*)(g_dw + (size_t)(b * 64 + c) * HW + y * WW + x0);
    *dst = make_float4(a0, a1, a2, a3);
}

// ---------------------------------------------------------------------------
// Kernel B: pointwise 1x1, 64->64, FFMA2 over output-channel pairs.
// grid (64, 4), block 256.
// ---------------------------------------------------------------------------
__global__ __launch_bounds__(256) void k_pw(const float* __restrict__ wpw) {
    __shared__ u64 wsh2[64 * 8];   // [c][opl] = (w[oc0+2opl][c], w[oc0+2opl+1][c])
    int tid = threadIdx.x;
    int oc0 = blockIdx.y * 16;
    for (int i = tid; i < 512; i += 256) {
        int c = i >> 3, opl = i & 7;
        wsh2[i] = pk(wpw[(oc0 + 2 * opl) * 64 + c], wpw[(oc0 + 2 * opl + 1) * 64 + c]);
    }
    __syncthreads();

    int quad = blockIdx.x * 256 + tid;    // 0..16383
    int b  = quad >> 12;
    int p4 = (quad & 4095) * 4;
    const float* src = g_dw + (size_t)b * CHW + p4;

    u64 acc[8][4];
#pragma unroll
    for (int o = 0; o < 8; o++)
#pragma unroll
        for (int p = 0; p < 4; p++) acc[o][p] = 0ULL;

#pragma unroll 4
    for (int c = 0; c < 64; c++) {
        float4 v = *(const float4*)(src + c * HW);
        u64 d0 = dup2(v.x), d1 = dup2(v.y), d2 = dup2(v.z), d3 = dup2(v.w);
        const u64* wr = &wsh2[c * 8];
#pragma unroll
        for (int o = 0; o < 8; o++) {
            u64 w2 = wr[o];
            acc[o][0] = fma2(w2, d0, acc[o][0]);
            acc[o][1] = fma2(w2, d1, acc[o][1]);
            acc[o][2] = fma2(w2, d2, acc[o][2]);
            acc[o][3] = fma2(w2, d3, acc[o][3]);
        }
    }

    float* dst = g_h + (size_t)b * CHW + p4;
#pragma unroll
    for (int o = 0; o < 8; o++) {
        float l0, h0, l1, h1, l2, h2, l3, h3;
        up(acc[o][0], l0, h0); up(acc[o][1], l1, h1);
        up(acc[o][2], l2, h2); up(acc[o][3], l3, h3);
        *(float4*)(dst + (oc0 + 2 * o)     * HW) = make_float4(l0, l1, l2, l3);
        *(float4*)(dst + (oc0 + 2 * o + 1) * HW) = make_float4(h0, h1, h2, h3);
    }
}

// ---------------------------------------------------------------------------
// Kernel C: reduce 64->16 (FFMA2 over cr-pairs) + deterministic BN partials.
// ---------------------------------------------------------------------------
__global__ void k_reduce(const float* __restrict__ x, const float* __restrict__ wred) {
    __shared__ u64 wt2[64 * 8];     // [c][crp] = (w[2crp][c], w[2crp+1][c])
    __shared__ float sm_s[16][8];
    __shared__ float sm_q[16][8];
    int tid = threadIdx.x;
    for (int i = tid; i < 512; i += 256) {
        int c = i >> 3, crp = i & 7;
        wt2[i] = pk(wred[(2 * crp) * 64 + c], wred[(2 * crp + 1) * 64 + c]);
    }
    __syncthreads();

    int pix = blockIdx.x * 256 + tid;     // 0..65535
    int b = pix >> 14;
    int p = pix & 16383;
    const float* src = x + (size_t)b * CHW + p;

    u64 acc[8];
#pragma unroll
    for (int i = 0; i < 8; i++) acc[i] = 0ULL;

#pragma unroll 4
    for (int c = 0; c < 64; c++) {
        u64 d = dup2(src[c * HW]);
        const u64* wr = &wt2[c * 8];
#pragma unroll
        for (int crp = 0; crp < 8; crp++)
            acc[crp] = fma2(wr[crp], d, acc[crp]);
    }

    float av[16];
#pragma unroll
    for (int crp = 0; crp < 8; crp++) up(acc[crp], av[2 * crp], av[2 * crp + 1]);

    float* rdst = g_r + (size_t)b * (CRR * HW) + p;
#pragma unroll
    for (int cr = 0; cr < 16; cr++) rdst[cr * HW] = av[cr];

    int lane = tid & 31, warp = tid >> 5;
#pragma unroll
    for (int cr = 0; cr < 16; cr++) {
        float s = av[cr];
        float q = av[cr] * av[cr];
#pragma unroll
        for (int off = 16; off; off >>= 1) {
            s += __shfl_down_sync(0xFFFFFFFFu, s, off);
            q += __shfl_down_sync(0xFFFFFFFFu, q, off);
        }
        if (lane == 0) { sm_s[cr][warp] = s; sm_q[cr][warp] = q; }
    }
    __syncthreads();
    if (tid < 16) {
        float s = 0.f, q = 0.f;
#pragma unroll
        for (int w = 0; w < 8; w++) { s += sm_s[tid][w]; q += sm_q[tid][w]; }
        g_psum[tid * STAT_BLOCKS + blockIdx.x] = s;
        g_psq [tid * STAT_BLOCKS + blockIdx.x] = q;
    }
}

// ---------------------------------------------------------------------------
// Kernel D (main, fused): BN-finalize prologue -> BN+ReLU -> span GEMM ->
// involution. 2 x-adjacent pixels per thread; kern-gen + involution
// interleaved per tap so weights are loaded once per tap per thread (LDS.128)
// and kern values never hit memory.
// Tile: 16y x 32x per block (16x16 threads). grid (4, 8, B*G).
// ---------------------------------------------------------------------------
__global__ __launch_bounds__(256) void k_main(const float* __restrict__ wspan,
                                              float* __restrict__ out,
                                              const float* __restrict__ gamma,
                                              const float* __restrict__ beta) {
    __shared__ ulonglong2 hsh[22 * 38];     // halo tile, (ch01, ch23) packed
    __shared__ ulonglong2 wsp4[49 * 4];     // span weights: per kk, 4 ulonglong2 (16 floats)
    __shared__ float ssc[16], sbi[16];

    int tid = threadIdx.x;
    int b = blockIdx.z >> 4;
    int g = blockIdx.z & 15;

    // stage span weights for this group: 784 floats = 196 ulonglong2
    {
        const ulonglong2* wsrc = (const ulonglong2*)(wspan + g * 784);
        if (tid < 196) wsp4[tid] = wsrc[tid];
    }

    // stage h tile (4 ch of this group) with halo 3: 22 rows x 38 cols
    int y0 = blockIdx.y * 16 - 3, x0 = blockIdx.x * 32 - 3;
    const float* hb = g_h + (size_t)b * CHW + (g * 4) * HW;
    for (int i = tid; i < 22 * 38; i += 256) {
        int ly = i / 38, lx = i - ly * 38;
        int yy = y0 + ly, xx = x0 + lx;
        u64 a = 0ULL, c = 0ULL;
        if ((unsigned)yy < (unsigned)HH && (unsigned)xx < (unsigned)WW) {
            int off = yy * WW + xx;
            a = pk(hb[off], hb[off + HW]);
            c = pk(hb[off + 2 * HW], hb[off + 3 * HW]);
        }
        ulonglong2 hv; hv.x = a; hv.y = c;
        hsh[i] = hv;
    }

    // BN finalize (redundant per block; deterministic fixed-order sums).
    int warp = tid >> 5, lane = tid & 31;
#pragma unroll
    for (int rep = 0; rep < 2; rep++) {
        int cr = warp + rep * 8;
        float s = 0.f, q = 0.f;
        for (int i = lane; i < STAT_BLOCKS; i += 32) {
            s += g_psum[cr * STAT_BLOCKS + i];
            q += g_psq [cr * STAT_BLOCKS + i];
        }
#pragma unroll
        for (int off = 16; off; off >>= 1) {
            s += __shfl_down_sync(0xFFFFFFFFu, s, off);
            q += __shfl_down_sync(0xFFFFFFFFu, q, off);
        }
        if (lane == 0) {
            const float inv = 1.0f / (float)NPIX;
            float mean = s * inv;
            float var  = q * inv - mean * mean;
            float sc = gamma[cr] * rsqrtf(var + EPSBN);
            ssc[cr] = sc;
            sbi[cr] = beta[cr] - mean * sc;
        }
    }
    __syncthreads();

    int ty  = tid >> 4;            // 0..15
    int tx2 = (tid & 15) * 2;      // 0..30 (two x-adjacent pixels)
    int y = blockIdx.y * 16 + ty;
    int x = blockIdx.x * 32 + tx2;

    // normalized + ReLU'd r for both pixels, packed into cr-pairs
    const float* rb = g_r + (size_t)b * (CRR * HW) + y * WW + x;
    u64 rnA[8], rnB[8];
#pragma unroll
    for (int crp = 0; crp < 8; crp++) {
        int cr = 2 * crp;
        float2 e = *(const float2*)&rb[cr * HW];
        float2 o = *(const float2*)&rb[(cr + 1) * HW];
        float sc0 = ssc[cr], bi0 = sbi[cr];
        float sc1 = ssc[cr + 1], bi1 = sbi[cr + 1];
        rnA[crp] = pk(fmaxf(fmaf(e.x, sc0, bi0), 0.f), fmaxf(fmaf(o.x, sc1, bi1), 0.f));
        rnB[crp] = pk(fmaxf(fmaf(e.y, sc0, bi0), 0.f), fmaxf(fmaf(o.y, sc1, bi1), 0.f));
    }

    // fused kern-gen + involution over the 49 taps
    u64 accA01 = 0ULL, accA23 = 0ULL, accB01 = 0ULL, accB23 = 0ULL;
    const ulonglong2* wv = wsp4;
#pragma unroll 1
    for (int ky = 0; ky < 7; ky++) {
        const ulonglong2* hrow = &hsh[(ty + ky) * 38 + tx2];
#pragma unroll
        for (int kx = 0; kx < 7; kx++) {
            ulonglong2 wA = wv[0];
            ulonglong2 wB = wv[1];
            wv += 2;
            // pixel A kern value
            u64 sA = mul2(wA.x, rnA[0]);
            sA = fma2(wA.y, rnA[1], sA);
            sA = fma2(wB.x, rnA[2], sA);
            sA = fma2(wB.y, rnA[3], sA);
            // pixel B kern value (same weights)
            u64 sB = mul2(wA.x, rnB[0]);
            sB = fma2(wA.y, rnB[1], sB);
            sB = fma2(wB.x, rnB[2], sB);
            sB = fma2(wB.y, rnB[3], sB);
            ulonglong2 wC = wv[0];
            ulonglong2 wD = wv[1];
            wv += 2;
            sA = fma2(wC.x, rnA[4], sA);
            sA = fma2(wC.y, rnA[5], sA);
            sA = fma2(wD.x, rnA[6], sA);
            sA = fma2(wD.y, rnA[7], sA);
            sB = fma2(wC.x, rnB[4], sB);
            sB = fma2(wC.y, rnB[5], sB);
            sB = fma2(wD.x, rnB[6], sB);
            sB = fma2(wD.y, rnB[7], sB);
            float lA, hA, lB, hB;
            up(sA, lA, hA); up(sB, lB, hB);
            u64 kdA = dup2(lA + hA);
            u64 kdB = dup2(lB + hB);
            // involution taps
            ulonglong2 h0 = hrow[kx];
            ulonglong2 h1 = hrow[kx + 1];
            accA01 = fma2(kdA, h0.x, accA01);
            accA23 = fma2(kdA, h0.y, accA23);
            accB01 = fma2(kdB, h1.x, accB01);
            accB23 = fma2(kdB, h1.y, accB23);
        }
    }

    float a0, a1, a2, a3, b0, b1, b2, b3;
    up(accA01, a0, a1); up(accA23, a2, a3);
    up(accB01, b0, b1); up(accB23, b2, b3);
    float* ob = out + (size_t)b * CHW + (g * 4) * HW + y * WW + x;
    *(float2*)&ob[0]      = make_float2(a0, b0);
    *(float2*)&ob[HW]     = make_float2(a1, b1);
    *(float2*)&ob[2 * HW] = make_float2(a2, b2);
    *(float2*)&ob[3 * HW] = make_float2(a3, b3);
}

// ---------------------------------------------------------------------------
extern "C" void kernel_launch(void* const* d_in, const int* in_sizes, int n_in,
                              void* d_out, int out_size) {
    const float* x      = (const float*)d_in[0];   // input  [4,64,128,128]
    const float* w_dw   = (const float*)d_in[1];   // [64,1,3,3]
    const float* w_pw   = (const float*)d_in[2];   // [64,64]
    const float* gamma  = (const float*)d_in[3];   // [16]
    const float* beta   = (const float*)d_in[4];   // [16]
    const float* w_red  = (const float*)d_in[5];   // [16,64]
    const float* w_span = (const float*)d_in[6];   // [784,16]
    float* out = (float*)d_out;

    k_dw<<<4096, 256>>>(x, w_dw);
    k_pw<<<dim3(64, 4), 256>>>(w_pw);
    k_reduce<<<STAT_BLOCKS, 256>>>(x, w_red);
    k_main<<<dim3(4, 8, BB * GG), 256>>>(w_span, out, gamma, beta);
}